// round 7
// baseline (speedup 1.0000x reference)
#include <cuda_runtime.h>
#include <cuda_fp16.h>

#define HID 128
#define MAX_NODES 40000
#define CAP 96           // padded bucket capacity per destination node
#define EPI 16           // edges per gather iteration

// Scratch (no allocation allowed -> device globals; zero-initialized at load)
__device__ float  g_s[MAX_NODES];                 // x[i] . w[:128]
__device__ float  g_t[MAX_NODES];                 // x[i] . w[128:]
__device__ __half g_xh[(size_t)MAX_NODES * HID];  // f16 copy of x for gathers
__device__ int    g_cursor[MAX_NODES];            // per-dest fill cursor (restored to 0 by gather)
__device__ int    g_bucket[(size_t)MAX_NODES * CAP]; // source ids per dest (padded)

// ---------------------------------------------------------------------------
// 1) Fused front kernel, role-split grid:
//    blocks [0, node_blocks): one warp per node -> s,t dots + f16 convert
//    blocks [node_blocks, ..): 4 edges per thread -> bucket placement
//    (disjoint outputs; g_cursor is 0 on entry, maintained by gather_kernel)
// ---------------------------------------------------------------------------
__global__ void front_kernel(const float* __restrict__ x,
                             const float* __restrict__ att_w,
                             const int* __restrict__ edge_index,
                             int n_nodes, int n_edges, int node_blocks) {
    if ((int)blockIdx.x < node_blocks) {
        // ---- prologue role ----
        int gwarp = (blockIdx.x * blockDim.x + threadIdx.x) >> 5;
        int lane  = threadIdx.x & 31;
        if (gwarp >= n_nodes) return;

        const float4* xr = reinterpret_cast<const float4*>(x + (size_t)gwarp * HID);
        const float4* w0 = reinterpret_cast<const float4*>(att_w);
        const float4* w1 = reinterpret_cast<const float4*>(att_w + HID);

        float4 xv = xr[lane];
        float4 a  = w0[lane];
        float4 b  = w1[lane];

        float s = xv.x * a.x + xv.y * a.y + xv.z * a.z + xv.w * a.w;
        float t = xv.x * b.x + xv.y * b.y + xv.z * b.z + xv.w * b.w;

        #pragma unroll
        for (int off = 16; off; off >>= 1) {
            s += __shfl_xor_sync(0xffffffffu, s, off);
            t += __shfl_xor_sync(0xffffffffu, t, off);
        }
        if (lane == 0) {
            g_s[gwarp] = s;
            g_t[gwarp] = t;
        }

        __half2 h01 = __floats2half2_rn(xv.x, xv.y);
        __half2 h23 = __floats2half2_rn(xv.z, xv.w);
        __half2* xh = reinterpret_cast<__half2*>(g_xh + (size_t)gwarp * HID);
        xh[lane * 2 + 0] = h01;
        xh[lane * 2 + 1] = h23;
    } else {
        // ---- bucket role: 4 edges per thread ----
        int tquad = (blockIdx.x - node_blocks) * blockDim.x + threadIdx.x;
        int base = tquad * 4;
        if (base >= n_edges) return;

        int4 r4 = *reinterpret_cast<const int4*>(edge_index + base);
        int4 c4 = *reinterpret_cast<const int4*>(edge_index + n_edges + base);
        int rr[4] = {r4.x, r4.y, r4.z, r4.w};
        int cc[4] = {c4.x, c4.y, c4.z, c4.w};

        int pos[4];
        #pragma unroll
        for (int j = 0; j < 4; j++)
            pos[j] = atomicAdd(&g_cursor[cc[j]], 1);

        #pragma unroll
        for (int j = 0; j < 4; j++)
            if (pos[j] < CAP)   // distribution guarantees no overflow; clamp for safety
                g_bucket[(size_t)cc[j] * CAP + pos[j]] = rr[j];
    }
}

// ---------------------------------------------------------------------------
// 2) Gather: one warp per dest node, EPI edges per iteration, predicated
//    gathers (no dummy traffic). Restores g_cursor[c] = 0 for the next replay.
// ---------------------------------------------------------------------------
__global__ void gather_kernel(const float* __restrict__ x,
                              const float* __restrict__ att_b,
                              const float* __restrict__ eps,
                              float* __restrict__ out,
                              int n_nodes) {
    int gwarp = (blockIdx.x * blockDim.x + threadIdx.x) >> 5;
    int lane  = threadIdx.x & 31;
    if (gwarp >= n_nodes) return;

    int c   = gwarp;
    int cnt = g_cursor[c];
    if (cnt > CAP) cnt = CAP;
    if (lane == 0) g_cursor[c] = 0;    // restore invariant for next graph replay

    float e    = eps[0];
    float coef = 1.0f - e;
    float bb   = att_b[0];
    float tc   = g_t[c];

    const int4* bucket = reinterpret_cast<const int4*>(g_bucket + (size_t)c * CAP);

    float ax = 0.0f, ay = 0.0f, az = 0.0f, aw = 0.0f;

    for (int i = 0; i < cnt; i += EPI) {
        int m = cnt - i;
        if (m > EPI) m = EPI;

        // broadcast loads of EPI source ids (four int4s, within padded CAP)
        int rr[EPI];
        #pragma unroll
        for (int q = 0; q < EPI / 4; q++) {
            int4 v = bucket[(i >> 2) + q];
            rr[q * 4 + 0] = v.x; rr[q * 4 + 1] = v.y;
            rr[q * 4 + 2] = v.z; rr[q * 4 + 3] = v.w;
        }

        // lanes 0..EPI-1 compute per-edge scales; broadcast via shfl
        float scale_own = 0.0f;
        if (lane < m)
            scale_own = coef * tanhf(g_s[rr[lane]] + tc + bb);

        // predicated independent f16 gathers (MLP = m, no tail waste)
        float2 hv[EPI];
        #pragma unroll
        for (int j = 0; j < EPI; j++) {
            hv[j] = make_float2(0.0f, 0.0f);
            if (j < m) {
                const float2* xh2 = reinterpret_cast<const float2*>(g_xh + (size_t)rr[j] * HID);
                hv[j] = xh2[lane];
            }
        }

        #pragma unroll
        for (int j = 0; j < EPI; j++) {
            float scale = __shfl_sync(0xffffffffu, scale_own, j);
            __half2 h01 = *reinterpret_cast<__half2*>(&hv[j].x);
            __half2 h23 = *reinterpret_cast<__half2*>(&hv[j].y);
            float2 f01 = __half22float2(h01);
            float2 f23 = __half22float2(h23);
            ax += scale * f01.x;    // scale=0 for j>=m lanes' shfl? (j<m guard below not needed:
            ay += scale * f01.y;    //  scale_own=0 for lane>=m, hv=0 for j>=m -> contributes 0)
            az += scale * f23.x;
            aw += scale * f23.y;
        }
    }

    // epilogue: out[c] = eps * x[c] + acc   (acc already carries (1-eps))
    float4 xv = reinterpret_cast<const float4*>(x + (size_t)c * HID)[lane];
    float4 ov;
    ov.x = e * xv.x + ax;
    ov.y = e * xv.y + ay;
    ov.z = e * xv.z + az;
    ov.w = e * xv.w + aw;
    reinterpret_cast<float4*>(out + (size_t)c * HID)[lane] = ov;
}

// ---------------------------------------------------------------------------
// Launch
// ---------------------------------------------------------------------------
extern "C" void kernel_launch(void* const* d_in, const int* in_sizes, int n_in,
                              void* d_out, int out_size) {
    const float* x     = (const float*)d_in[0];
    const int*   ei    = (const int*)d_in[1];
    const float* att_w = (const float*)d_in[2];
    const float* att_b = (const float*)d_in[3];
    const float* eps   = (const float*)d_in[4];
    float*       out   = (float*)d_out;

    int n_nodes = in_sizes[0] / HID;
    int n_edges = in_sizes[1] / 2;

    int threads = 256;
    int wpb = threads / 32;

    {   // 1) fused: node dots + f16 convert || edge bucketing
        int node_blocks  = (n_nodes + wpb - 1) / wpb;
        int quads        = (n_edges + 3) / 4;
        int edge_blocks  = (quads + threads - 1) / threads;
        front_kernel<<<node_blocks + edge_blocks, threads>>>(
            x, att_w, ei, n_nodes, n_edges, node_blocks);
    }
    {   // 2) per-dest gather + epilogue (warp per node)
        int blocks = (n_nodes + wpb - 1) / wpb;
        gather_kernel<<<blocks, threads>>>(x, att_b, eps, out, n_nodes);
    }
}

// round 8
// speedup vs baseline: 1.0954x; 1.0954x over previous
#include <cuda_runtime.h>
#include <cuda_fp16.h>

#define HID 128
#define MAX_NODES 40000
#define CAP 96           // padded bucket capacity per destination node
#define EPI 8            // edges per gather iteration (proven sweet spot)

// Scratch (no allocation allowed -> device globals; zero-initialized at load)
__device__ float  g_s[MAX_NODES];                 // x[i] . w[:128]
__device__ float  g_t[MAX_NODES];                 // x[i] . w[128:]
__device__ __half g_xh[(size_t)MAX_NODES * HID];  // f16 copy of x for gathers
__device__ int    g_cursor[MAX_NODES];            // per-dest fill cursor (restored to 0 by gather)
__device__ int    g_bucket[(size_t)MAX_NODES * CAP]; // source ids per dest (padded)

// ---------------------------------------------------------------------------
// 1) Fused front kernel, role-split grid:
//    blocks [0, node_blocks): one warp per node -> s,t dots + f16 convert
//    blocks [node_blocks, ..): 4 edges per thread -> bucket placement
// ---------------------------------------------------------------------------
__global__ void front_kernel(const float* __restrict__ x,
                             const float* __restrict__ att_w,
                             const int* __restrict__ edge_index,
                             int n_nodes, int n_edges, int node_blocks) {
    if ((int)blockIdx.x < node_blocks) {
        // ---- prologue role ----
        int gwarp = (blockIdx.x * blockDim.x + threadIdx.x) >> 5;
        int lane  = threadIdx.x & 31;
        if (gwarp >= n_nodes) return;

        const float4* xr = reinterpret_cast<const float4*>(x + (size_t)gwarp * HID);
        const float4* w0 = reinterpret_cast<const float4*>(att_w);
        const float4* w1 = reinterpret_cast<const float4*>(att_w + HID);

        float4 xv = xr[lane];
        float4 a  = w0[lane];
        float4 b  = w1[lane];

        float s = xv.x * a.x + xv.y * a.y + xv.z * a.z + xv.w * a.w;
        float t = xv.x * b.x + xv.y * b.y + xv.z * b.z + xv.w * b.w;

        #pragma unroll
        for (int off = 16; off; off >>= 1) {
            s += __shfl_xor_sync(0xffffffffu, s, off);
            t += __shfl_xor_sync(0xffffffffu, t, off);
        }
        if (lane == 0) {
            g_s[gwarp] = s;
            g_t[gwarp] = t;
        }

        __half2 h01 = __floats2half2_rn(xv.x, xv.y);
        __half2 h23 = __floats2half2_rn(xv.z, xv.w);
        __half2* xh = reinterpret_cast<__half2*>(g_xh + (size_t)gwarp * HID);
        xh[lane * 2 + 0] = h01;
        xh[lane * 2 + 1] = h23;
    } else {
        // ---- bucket role: 4 edges per thread ----
        int tquad = (blockIdx.x - node_blocks) * blockDim.x + threadIdx.x;
        int base = tquad * 4;
        if (base >= n_edges) return;

        int4 r4 = *reinterpret_cast<const int4*>(edge_index + base);
        int4 c4 = *reinterpret_cast<const int4*>(edge_index + n_edges + base);
        int rr[4] = {r4.x, r4.y, r4.z, r4.w};
        int cc[4] = {c4.x, c4.y, c4.z, c4.w};

        int pos[4];
        #pragma unroll
        for (int j = 0; j < 4; j++)
            pos[j] = atomicAdd(&g_cursor[cc[j]], 1);

        #pragma unroll
        for (int j = 0; j < 4; j++)
            if (pos[j] < CAP)   // distribution guarantees no overflow; clamp for safety
                g_bucket[(size_t)cc[j] * CAP + pos[j]] = rr[j];
    }
}

// ---------------------------------------------------------------------------
// 2) Gather: one warp per dest node, EPI=8 edges per iteration.
//    Unpredicated gathers; tail lanes use a duplicate (L1-resident) index.
//    Restores g_cursor[c] = 0 for the next graph replay.
// ---------------------------------------------------------------------------
__global__ void gather_kernel(const float* __restrict__ x,
                              const float* __restrict__ att_b,
                              const float* __restrict__ eps,
                              float* __restrict__ out,
                              int n_nodes) {
    int gwarp = (blockIdx.x * blockDim.x + threadIdx.x) >> 5;
    int lane  = threadIdx.x & 31;
    if (gwarp >= n_nodes) return;

    int c   = gwarp;
    int cnt = g_cursor[c];
    if (cnt > CAP) cnt = CAP;
    if (lane == 0) g_cursor[c] = 0;    // restore invariant for next graph replay

    float e    = eps[0];
    float coef = 1.0f - e;
    float bb   = att_b[0];
    float tc   = g_t[c];

    const int4* bucket = reinterpret_cast<const int4*>(g_bucket + (size_t)c * CAP);

    float ax = 0.0f, ay = 0.0f, az = 0.0f, aw = 0.0f;

    for (int i = 0; i < cnt; i += EPI) {
        int m = cnt - i;
        if (m > EPI) m = EPI;

        // broadcast loads of EPI source ids (two int4s)
        int rr[EPI];
        {
            int4 q0 = bucket[(i >> 2) + 0];
            rr[0] = q0.x; rr[1] = q0.y; rr[2] = q0.z; rr[3] = q0.w;
            int4 q1 = (m > 4) ? bucket[(i >> 2) + 1] : q0;
            rr[4] = q1.x; rr[5] = q1.y; rr[6] = q1.z; rr[7] = q1.w;
        }
        #pragma unroll
        for (int j = 0; j < EPI; j++)
            if (j >= m) rr[j] = rr[0];   // duplicate index: L1-resident, ~free

        // lanes 0..EPI-1 compute per-edge scales; broadcast via shfl
        float scale_own = 0.0f;
        if (lane < m)
            scale_own = coef * tanhf(g_s[rr[lane]] + tc + bb);

        // unconditional independent f16 gathers (MLP = EPI)
        float2 hv[EPI];
        #pragma unroll
        for (int j = 0; j < EPI; j++) {
            const float2* xh2 = reinterpret_cast<const float2*>(g_xh + (size_t)rr[j] * HID);
            hv[j] = xh2[lane];
        }

        #pragma unroll
        for (int j = 0; j < EPI; j++) {
            float scale = __shfl_sync(0xffffffffu, scale_own, j);
            if (j < m) {
                __half2 h01 = *reinterpret_cast<__half2*>(&hv[j].x);
                __half2 h23 = *reinterpret_cast<__half2*>(&hv[j].y);
                float2 f01 = __half22float2(h01);
                float2 f23 = __half22float2(h23);
                ax += scale * f01.x;
                ay += scale * f01.y;
                az += scale * f23.x;
                aw += scale * f23.y;
            }
        }
    }

    // epilogue: out[c] = eps * x[c] + acc   (acc already carries (1-eps))
    float4 xv = reinterpret_cast<const float4*>(x + (size_t)c * HID)[lane];
    float4 ov;
    ov.x = e * xv.x + ax;
    ov.y = e * xv.y + ay;
    ov.z = e * xv.z + az;
    ov.w = e * xv.w + aw;
    reinterpret_cast<float4*>(out + (size_t)c * HID)[lane] = ov;
}

// ---------------------------------------------------------------------------
// Launch
// ---------------------------------------------------------------------------
extern "C" void kernel_launch(void* const* d_in, const int* in_sizes, int n_in,
                              void* d_out, int out_size) {
    const float* x     = (const float*)d_in[0];
    const int*   ei    = (const int*)d_in[1];
    const float* att_w = (const float*)d_in[2];
    const float* att_b = (const float*)d_in[3];
    const float* eps   = (const float*)d_in[4];
    float*       out   = (float*)d_out;

    int n_nodes = in_sizes[0] / HID;
    int n_edges = in_sizes[1] / 2;

    int threads = 256;
    int wpb = threads / 32;

    {   // 1) fused: node dots + f16 convert || edge bucketing
        int node_blocks  = (n_nodes + wpb - 1) / wpb;
        int quads        = (n_edges + 3) / 4;
        int edge_blocks  = (quads + threads - 1) / threads;
        front_kernel<<<node_blocks + edge_blocks, threads>>>(
            x, att_w, ei, n_nodes, n_edges, node_blocks);
    }
    {   // 2) per-dest gather + epilogue (warp per node)
        int blocks = (n_nodes + wpb - 1) / wpb;
        gather_kernel<<<blocks, threads>>>(x, att_b, eps, out, n_nodes);
    }
}

// round 9
// speedup vs baseline: 2.1223x; 1.9376x over previous
#include <cuda_runtime.h>
#include <cuda_fp16.h>

#define HID 128
#define MAX_NODES 40000
#define CAP 96           // padded bucket capacity per destination node
#define EPI 8            // edges per gather iteration (proven sweet spot)

// Scratch (no allocation allowed -> device globals; zero-initialized at load)
__device__ float  g_s[MAX_NODES];                 // x[i] . w[:128]
__device__ float  g_t[MAX_NODES];                 // x[i] . w[128:]
__device__ __half g_xh[(size_t)MAX_NODES * HID];  // f16 copy of x for gathers
__device__ int    g_cursor[MAX_NODES];            // per-dest fill cursor (zeroed by prologue)
__device__ int    g_bucket[(size_t)MAX_NODES * CAP]; // source ids per dest (padded)

// ---------------------------------------------------------------------------
// 1) Prologue: one warp per TWO nodes (MLP=2 on the x-row loads).
//    s[i], t[i] = dots with att_w halves; g_xh = f16(x); zero cursors.
// ---------------------------------------------------------------------------
__global__ void prologue_kernel(const float* __restrict__ x,
                                const float* __restrict__ att_w,
                                int n_nodes) {
    int gwarp = (blockIdx.x * blockDim.x + threadIdx.x) >> 5;
    int lane  = threadIdx.x & 31;
    int nA = gwarp * 2;
    int nB = nA + 1;
    if (nA >= n_nodes) return;
    bool hasB = (nB < n_nodes);
    int nBs = hasB ? nB : nA;   // safe duplicate

    const float4* xrA = reinterpret_cast<const float4*>(x + (size_t)nA  * HID);
    const float4* xrB = reinterpret_cast<const float4*>(x + (size_t)nBs * HID);
    const float4* w0  = reinterpret_cast<const float4*>(att_w);
    const float4* w1  = reinterpret_cast<const float4*>(att_w + HID);

    float4 xa = xrA[lane];
    float4 xb = xrB[lane];
    float4 a  = w0[lane];
    float4 b  = w1[lane];

    float sA = xa.x * a.x + xa.y * a.y + xa.z * a.z + xa.w * a.w;
    float tA = xa.x * b.x + xa.y * b.y + xa.z * b.z + xa.w * b.w;
    float sB = xb.x * a.x + xb.y * a.y + xb.z * a.z + xb.w * a.w;
    float tB = xb.x * b.x + xb.y * b.y + xb.z * b.z + xb.w * b.w;

    #pragma unroll
    for (int off = 16; off; off >>= 1) {
        sA += __shfl_xor_sync(0xffffffffu, sA, off);
        tA += __shfl_xor_sync(0xffffffffu, tA, off);
        sB += __shfl_xor_sync(0xffffffffu, sB, off);
        tB += __shfl_xor_sync(0xffffffffu, tB, off);
    }
    if (lane == 0) {
        g_s[nA] = sA;
        g_t[nA] = tA;
        g_cursor[nA] = 0;
        if (hasB) {
            g_s[nB] = sB;
            g_t[nB] = tB;
            g_cursor[nB] = 0;
        }
    }

    __half2* xhA = reinterpret_cast<__half2*>(g_xh + (size_t)nA * HID);
    xhA[lane * 2 + 0] = __floats2half2_rn(xa.x, xa.y);
    xhA[lane * 2 + 1] = __floats2half2_rn(xa.z, xa.w);
    if (hasB) {
        __half2* xhB = reinterpret_cast<__half2*>(g_xh + (size_t)nB * HID);
        xhB[lane * 2 + 0] = __floats2half2_rn(xb.x, xb.y);
        xhB[lane * 2 + 1] = __floats2half2_rn(xb.z, xb.w);
    }
}

// ---------------------------------------------------------------------------
// 2) Bucket: 8 edges per thread (2x int4 loads per array, 8 independent
//    atomics in flight). pos = atomicAdd(cursor[c]); bucket[c*CAP+pos] = r.
// ---------------------------------------------------------------------------
__global__ void bucket_kernel(const int* __restrict__ edge_index, int n_edges) {
    int t = blockIdx.x * blockDim.x + threadIdx.x;
    int base = t * 8;
    if (base >= n_edges) return;

    if (base + 8 <= n_edges) {
        int4 r0 = *reinterpret_cast<const int4*>(edge_index + base);
        int4 r1 = *reinterpret_cast<const int4*>(edge_index + base + 4);
        int4 c0 = *reinterpret_cast<const int4*>(edge_index + n_edges + base);
        int4 c1 = *reinterpret_cast<const int4*>(edge_index + n_edges + base + 4);
        int rr[8] = {r0.x, r0.y, r0.z, r0.w, r1.x, r1.y, r1.z, r1.w};
        int cc[8] = {c0.x, c0.y, c0.z, c0.w, c1.x, c1.y, c1.z, c1.w};

        int pos[8];
        #pragma unroll
        for (int j = 0; j < 8; j++)
            pos[j] = atomicAdd(&g_cursor[cc[j]], 1);

        #pragma unroll
        for (int j = 0; j < 8; j++)
            if (pos[j] < CAP)
                g_bucket[(size_t)cc[j] * CAP + pos[j]] = rr[j];
    } else {
        for (int e = base; e < n_edges; e++) {
            int r = edge_index[e];
            int c = edge_index[n_edges + e];
            int pos = atomicAdd(&g_cursor[c], 1);
            if (pos < CAP)
                g_bucket[(size_t)c * CAP + pos] = r;
        }
    }
}

// ---------------------------------------------------------------------------
// 3) Gather (verbatim R6): one warp per dest node, EPI=8 per iteration,
//    unpredicated gathers with duplicate-index tail. No cursor reset.
// ---------------------------------------------------------------------------
__global__ void gather_kernel(const float* __restrict__ x,
                              const float* __restrict__ att_b,
                              const float* __restrict__ eps,
                              float* __restrict__ out,
                              int n_nodes) {
    int gwarp = (blockIdx.x * blockDim.x + threadIdx.x) >> 5;
    int lane  = threadIdx.x & 31;
    if (gwarp >= n_nodes) return;

    int c   = gwarp;
    int cnt = g_cursor[c];
    if (cnt > CAP) cnt = CAP;

    float e    = eps[0];
    float coef = 1.0f - e;
    float bb   = att_b[0];
    float tc   = g_t[c];

    const int4* bucket = reinterpret_cast<const int4*>(g_bucket + (size_t)c * CAP);

    float ax = 0.0f, ay = 0.0f, az = 0.0f, aw = 0.0f;

    for (int i = 0; i < cnt; i += EPI) {
        int m = cnt - i;
        if (m > EPI) m = EPI;

        int rr[EPI];
        {
            int4 q0 = bucket[(i >> 2) + 0];
            rr[0] = q0.x; rr[1] = q0.y; rr[2] = q0.z; rr[3] = q0.w;
            int4 q1 = (m > 4) ? bucket[(i >> 2) + 1] : q0;
            rr[4] = q1.x; rr[5] = q1.y; rr[6] = q1.z; rr[7] = q1.w;
        }
        #pragma unroll
        for (int j = 0; j < EPI; j++)
            if (j >= m) rr[j] = rr[0];   // duplicate index: L1-resident, ~free

        float scale_own = 0.0f;
        if (lane < m)
            scale_own = coef * tanhf(g_s[rr[lane]] + tc + bb);

        float2 hv[EPI];
        #pragma unroll
        for (int j = 0; j < EPI; j++) {
            const float2* xh2 = reinterpret_cast<const float2*>(g_xh + (size_t)rr[j] * HID);
            hv[j] = xh2[lane];
        }

        #pragma unroll
        for (int j = 0; j < EPI; j++) {
            float scale = __shfl_sync(0xffffffffu, scale_own, j);
            if (j < m) {
                __half2 h01 = *reinterpret_cast<__half2*>(&hv[j].x);
                __half2 h23 = *reinterpret_cast<__half2*>(&hv[j].y);
                float2 f01 = __half22float2(h01);
                float2 f23 = __half22float2(h23);
                ax += scale * f01.x;
                ay += scale * f01.y;
                az += scale * f23.x;
                aw += scale * f23.y;
            }
        }
    }

    float4 xv = reinterpret_cast<const float4*>(x + (size_t)c * HID)[lane];
    float4 ov;
    ov.x = e * xv.x + ax;
    ov.y = e * xv.y + ay;
    ov.z = e * xv.z + az;
    ov.w = e * xv.w + aw;
    reinterpret_cast<float4*>(out + (size_t)c * HID)[lane] = ov;
}

// ---------------------------------------------------------------------------
// Launch (R6 structure: prologue -> bucket -> gather)
// ---------------------------------------------------------------------------
extern "C" void kernel_launch(void* const* d_in, const int* in_sizes, int n_in,
                              void* d_out, int out_size) {
    const float* x     = (const float*)d_in[0];
    const int*   ei    = (const int*)d_in[1];
    const float* att_w = (const float*)d_in[2];
    const float* att_b = (const float*)d_in[3];
    const float* eps   = (const float*)d_in[4];
    float*       out   = (float*)d_out;

    int n_nodes = in_sizes[0] / HID;
    int n_edges = in_sizes[1] / 2;

    int threads = 256;
    int wpb = threads / 32;

    {   // 1) dots + f16 convert + zero cursors (warp per 2 nodes)
        int pairs = (n_nodes + 1) / 2;
        int blocks = (pairs + wpb - 1) / wpb;
        prologue_kernel<<<blocks, threads>>>(x, att_w, n_nodes);
    }
    {   // 2) bucket placement, 8 edges/thread
        int octs = (n_edges + 7) / 8;
        int blocks = (octs + threads - 1) / threads;
        bucket_kernel<<<blocks, threads>>>(ei, n_edges);
    }
    {   // 3) per-dest gather + epilogue (warp per node)
        int blocks = (n_nodes + wpb - 1) / wpb;
        gather_kernel<<<blocks, threads>>>(x, att_b, eps, out, n_nodes);
    }
}

// round 10
// speedup vs baseline: 2.2727x; 1.0709x over previous
#include <cuda_runtime.h>
#include <cuda_fp16.h>

#define HID 128
#define MAX_NODES 40000
#define CAP 96           // padded bucket capacity per destination node
#define EPI 8            // edges per gather iteration

// Scratch (no allocation allowed -> device globals; zero-initialized at load)
__device__ float  g_s[MAX_NODES];                 // x[i] . w[:128]
__device__ float  g_t[MAX_NODES];                 // x[i] . w[128:]
__device__ __half g_xh[(size_t)MAX_NODES * HID];  // f16 copy of x for gathers
__device__ int    g_cursor[MAX_NODES];            // per-dest fill cursor (zeroed by prologue)
__device__ int2   g_bucket[(size_t)MAX_NODES * CAP]; // {src id, scale bits} per dest

// ---------------------------------------------------------------------------
// 1) Prologue: one warp per TWO nodes (MLP=2 on the x-row loads).
//    s[i], t[i] = dots with att_w halves; g_xh = f16(x); zero cursors.
// ---------------------------------------------------------------------------
__global__ void prologue_kernel(const float* __restrict__ x,
                                const float* __restrict__ att_w,
                                int n_nodes) {
    int gwarp = (blockIdx.x * blockDim.x + threadIdx.x) >> 5;
    int lane  = threadIdx.x & 31;
    int nA = gwarp * 2;
    int nB = nA + 1;
    if (nA >= n_nodes) return;
    bool hasB = (nB < n_nodes);
    int nBs = hasB ? nB : nA;   // safe duplicate

    const float4* xrA = reinterpret_cast<const float4*>(x + (size_t)nA  * HID);
    const float4* xrB = reinterpret_cast<const float4*>(x + (size_t)nBs * HID);
    const float4* w0  = reinterpret_cast<const float4*>(att_w);
    const float4* w1  = reinterpret_cast<const float4*>(att_w + HID);

    float4 xa = xrA[lane];
    float4 xb = xrB[lane];
    float4 a  = w0[lane];
    float4 b  = w1[lane];

    float sA = xa.x * a.x + xa.y * a.y + xa.z * a.z + xa.w * a.w;
    float tA = xa.x * b.x + xa.y * b.y + xa.z * b.z + xa.w * b.w;
    float sB = xb.x * a.x + xb.y * a.y + xb.z * a.z + xb.w * a.w;
    float tB = xb.x * b.x + xb.y * b.y + xb.z * b.z + xb.w * b.w;

    #pragma unroll
    for (int off = 16; off; off >>= 1) {
        sA += __shfl_xor_sync(0xffffffffu, sA, off);
        tA += __shfl_xor_sync(0xffffffffu, tA, off);
        sB += __shfl_xor_sync(0xffffffffu, sB, off);
        tB += __shfl_xor_sync(0xffffffffu, tB, off);
    }
    if (lane == 0) {
        g_s[nA] = sA;
        g_t[nA] = tA;
        g_cursor[nA] = 0;
        if (hasB) {
            g_s[nB] = sB;
            g_t[nB] = tB;
            g_cursor[nB] = 0;
        }
    }

    __half2* xhA = reinterpret_cast<__half2*>(g_xh + (size_t)nA * HID);
    xhA[lane * 2 + 0] = __floats2half2_rn(xa.x, xa.y);
    xhA[lane * 2 + 1] = __floats2half2_rn(xa.z, xa.w);
    if (hasB) {
        __half2* xhB = reinterpret_cast<__half2*>(g_xh + (size_t)nB * HID);
        xhB[lane * 2 + 0] = __floats2half2_rn(xb.x, xb.y);
        xhB[lane * 2 + 1] = __floats2half2_rn(xb.z, xb.w);
    }
}

// ---------------------------------------------------------------------------
// 2) Bucket: 8 edges per thread. Computes the per-edge scale here (this
//    kernel is atomic-latency-bound with idle issue slots) and stores
//    {r, scale} so the gather kernel needs no g_s load / tanh / shfl.
// ---------------------------------------------------------------------------
__global__ void bucket_kernel(const int* __restrict__ edge_index,
                              const float* __restrict__ att_b,
                              const float* __restrict__ eps,
                              int n_edges) {
    int t = blockIdx.x * blockDim.x + threadIdx.x;
    int base = t * 8;
    if (base >= n_edges) return;

    float coef = 1.0f - eps[0];
    float bb   = att_b[0];

    if (base + 8 <= n_edges) {
        int4 r0 = *reinterpret_cast<const int4*>(edge_index + base);
        int4 r1 = *reinterpret_cast<const int4*>(edge_index + base + 4);
        int4 c0 = *reinterpret_cast<const int4*>(edge_index + n_edges + base);
        int4 c1 = *reinterpret_cast<const int4*>(edge_index + n_edges + base + 4);
        int rr[8] = {r0.x, r0.y, r0.z, r0.w, r1.x, r1.y, r1.z, r1.w};
        int cc[8] = {c0.x, c0.y, c0.z, c0.w, c1.x, c1.y, c1.z, c1.w};

        // independent random loads (MLP=16) + tanh, hidden under atomic latency
        float sv[8], tv[8];
        #pragma unroll
        for (int j = 0; j < 8; j++) { sv[j] = g_s[rr[j]]; tv[j] = g_t[cc[j]]; }

        int pos[8];
        #pragma unroll
        for (int j = 0; j < 8; j++)
            pos[j] = atomicAdd(&g_cursor[cc[j]], 1);

        #pragma unroll
        for (int j = 0; j < 8; j++) {
            float scale = coef * tanhf(sv[j] + tv[j] + bb);
            if (pos[j] < CAP)
                g_bucket[(size_t)cc[j] * CAP + pos[j]] =
                    make_int2(rr[j], __float_as_int(scale));
        }
    } else {
        for (int e = base; e < n_edges; e++) {
            int r = edge_index[e];
            int c = edge_index[n_edges + e];
            float scale = coef * tanhf(g_s[r] + g_t[c] + bb);
            int pos = atomicAdd(&g_cursor[c], 1);
            if (pos < CAP)
                g_bucket[(size_t)c * CAP + pos] = make_int2(r, __float_as_int(scale));
        }
    }
}

// ---------------------------------------------------------------------------
// 3) Gather: one warp per dest node, EPI=8 edges per iteration.
//    Bucket entries carry the precomputed scale: no g_s load, no tanh,
//    no shfl. Unpredicated gathers; tail uses duplicate index + guard.
// ---------------------------------------------------------------------------
__global__ void gather_kernel(const float* __restrict__ x,
                              const float* __restrict__ eps,
                              float* __restrict__ out,
                              int n_nodes) {
    int gwarp = (blockIdx.x * blockDim.x + threadIdx.x) >> 5;
    int lane  = threadIdx.x & 31;
    if (gwarp >= n_nodes) return;

    int c   = gwarp;
    int cnt = g_cursor[c];
    if (cnt > CAP) cnt = CAP;

    float e = eps[0];

    const int4* bucket = reinterpret_cast<const int4*>(g_bucket + (size_t)c * CAP);

    float ax = 0.0f, ay = 0.0f, az = 0.0f, aw = 0.0f;

    for (int i = 0; i < cnt; i += EPI) {
        int m = cnt - i;
        if (m > EPI) m = EPI;

        // broadcast loads of EPI {r, scale} entries (4 int4s = 8 int2 entries)
        int rr[EPI];
        float sc[EPI];
        #pragma unroll
        for (int q = 0; q < EPI / 2; q++) {
            // entry pair q: valid while 2q < m; else reuse quad 0 (L1-resident)
            int qi = (2 * q < m) ? ((i >> 1) + q) : (i >> 1);
            int4 v = bucket[qi];
            rr[2 * q + 0] = v.x; sc[2 * q + 0] = __int_as_float(v.y);
            rr[2 * q + 1] = v.z; sc[2 * q + 1] = __int_as_float(v.w);
        }

        // unconditional independent f16 gathers (MLP = EPI)
        float2 hv[EPI];
        #pragma unroll
        for (int j = 0; j < EPI; j++) {
            const float2* xh2 = reinterpret_cast<const float2*>(g_xh + (size_t)rr[j] * HID);
            hv[j] = xh2[lane];
        }

        #pragma unroll
        for (int j = 0; j < EPI; j++) {
            if (j < m) {
                __half2 h01 = *reinterpret_cast<__half2*>(&hv[j].x);
                __half2 h23 = *reinterpret_cast<__half2*>(&hv[j].y);
                float2 f01 = __half22float2(h01);
                float2 f23 = __half22float2(h23);
                float scale = sc[j];
                ax += scale * f01.x;
                ay += scale * f01.y;
                az += scale * f23.x;
                aw += scale * f23.y;
            }
        }
    }

    // epilogue: out[c] = eps * x[c] + acc   (acc already carries (1-eps))
    float4 xv = reinterpret_cast<const float4*>(x + (size_t)c * HID)[lane];
    float4 ov;
    ov.x = e * xv.x + ax;
    ov.y = e * xv.y + ay;
    ov.z = e * xv.z + az;
    ov.w = e * xv.w + aw;
    reinterpret_cast<float4*>(out + (size_t)c * HID)[lane] = ov;
}

// ---------------------------------------------------------------------------
// Launch (prologue -> bucket -> gather)
// ---------------------------------------------------------------------------
extern "C" void kernel_launch(void* const* d_in, const int* in_sizes, int n_in,
                              void* d_out, int out_size) {
    const float* x     = (const float*)d_in[0];
    const int*   ei    = (const int*)d_in[1];
    const float* att_w = (const float*)d_in[2];
    const float* att_b = (const float*)d_in[3];
    const float* eps   = (const float*)d_in[4];
    float*       out   = (float*)d_out;

    int n_nodes = in_sizes[0] / HID;
    int n_edges = in_sizes[1] / 2;

    int threads = 256;
    int wpb = threads / 32;

    {   // 1) dots + f16 convert + zero cursors (warp per 2 nodes)
        int pairs = (n_nodes + 1) / 2;
        int blocks = (pairs + wpb - 1) / wpb;
        prologue_kernel<<<blocks, threads>>>(x, att_w, n_nodes);
    }
    {   // 2) bucket placement + per-edge scale, 8 edges/thread
        int octs = (n_edges + 7) / 8;
        int blocks = (octs + threads - 1) / threads;
        bucket_kernel<<<blocks, threads>>>(ei, att_b, eps, n_edges);
    }
    {   // 3) per-dest gather + epilogue (warp per node)
        int blocks = (n_nodes + wpb - 1) / wpb;
        gather_kernel<<<blocks, threads>>>(x, eps, out, n_nodes);
    }
}